// round 1
// baseline (speedup 1.0000x reference)
#include <cuda_runtime.h>
#include <math.h>

#define Ln  128
#define Bn  4096
#define Dn  300
#define DP  320      // D padded to 5 tiles of 64
#define BT  32       // b rows per block (score kernel)
#define DT  64       // d tile
#define KT  30       // e (k) tile -> 10 exact tiles over 300
#define SST 305      // smem row stride (odd -> conflict-free row offsets)

// -------- device scratch (allocation-free per harness rules) --------
__device__ float g_Ws[DP * DP];     // symmetrized, zero-padded W + W^T
__device__ float g_A[Ln * Bn];      // 0.5 * s_l^T Ws s_l
__device__ float g_C[Ln * Bn];      // 0.5 * s_{l-1}^T Ws s_l   (l >= 1)

// ==================== kernel 1: Ws = W + W^T, zero-padded ====================
__global__ void symW_kernel(const float* __restrict__ W) {
    int idx = blockIdx.x * 256 + threadIdx.x;
    if (idx >= DP * DP) return;
    int e = idx / DP, d = idx % DP;
    float v = 0.0f;
    if (e < Dn && d < Dn) v = W[e * Dn + d] + W[d * Dn + e];
    g_Ws[idx] = v;
}

// ==================== kernel 2: fused scores ====================
// Per block: 32 consecutive b at fixed l. Computes u = Ws * s[l,b] tile-by-tile
// and immediately reduces  a = <s[l,b], u>,  c = <s[l-1,b], u>.
__global__ __launch_bounds__(128) void score_kernel(const float* __restrict__ S) {
    __shared__ __align__(16) float sS[BT * SST];  // s rows, cols 0..304 (300..304 zero)
    __shared__ __align__(16) float sW[KT * DT];   // Ws tile [e][d]

    const int l   = blockIdx.y;
    const int b0  = blockIdx.x * BT;
    const int tid = threadIdx.x;

    // ---- stage s[l, b0:b0+32, 0:300] into smem ----
    const float* base = S + ((size_t)l * Bn + b0) * Dn;
    for (int f = tid; f < BT * 75; f += 128) {           // 75 float4 per row
        int r = f / 75, c = (f % 75) * 4;
        float4 v = *(const float4*)(base + (size_t)r * Dn + c);
        float* p = &sS[r * SST + c];
        p[0] = v.x; p[1] = v.y; p[2] = v.z; p[3] = v.w;
    }
    for (int f = tid; f < BT * 5; f += 128) {            // zero pad cols 300..304
        int r = f / 5, c = 300 + (f % 5);
        sS[r * SST + c] = 0.0f;
    }
    __syncthreads();

    const int ty = tid >> 4;   // 0..7  -> rows {ty, ty+8, ty+16, ty+24}
    const int tx = tid & 15;   // 0..15 -> cols {tx, tx+16, tx+32, tx+48}

    float aAcc[4] = {0.f, 0.f, 0.f, 0.f};
    float cAcc[4] = {0.f, 0.f, 0.f, 0.f};

    for (int d0 = 0; d0 < DP; d0 += DT) {
        float acc[4][4] = {};                            // u micro-tile

        for (int e0 = 0; e0 < Dn; e0 += KT) {
            __syncthreads();
            // load Ws tile [e0:e0+30][d0:d0+64] -> 480 float4
            for (int f = tid; f < (KT * DT) / 4; f += 128) {
                int r = f >> 4, c = (f & 15) * 4;
                float4 v = *(const float4*)&g_Ws[(size_t)(e0 + r) * DP + d0 + c];
                *(float4*)&sW[r * DT + c] = v;
            }
            __syncthreads();

            #pragma unroll
            for (int ee = 0; ee < KT; ee++) {
                float sv[4], wv[4];
                #pragma unroll
                for (int i = 0; i < 4; i++) sv[i] = sS[(ty + 8 * i) * SST + e0 + ee];
                #pragma unroll
                for (int j = 0; j < 4; j++) wv[j] = sW[ee * DT + tx + 16 * j];
                #pragma unroll
                for (int i = 0; i < 4; i++)
                    #pragma unroll
                    for (int j = 0; j < 4; j++)
                        acc[i][j] = fmaf(sv[i], wv[j], acc[i][j]);
            }
        }

        // ---- dot epilogue for this d block ----
        #pragma unroll
        for (int i = 0; i < 4; i++) {
            const int row = ty + 8 * i;
            const int b   = b0 + row;
            #pragma unroll
            for (int j = 0; j < 4; j++) {
                const int d = d0 + tx + 16 * j;
                if (d < Dn) {
                    float u = acc[i][j];
                    aAcc[i] = fmaf(sS[row * SST + d], u, aAcc[i]);
                    if (l > 0)
                        cAcc[i] = fmaf(__ldg(&S[((size_t)(l - 1) * Bn + b) * Dn + d]), u, cAcc[i]);
                }
            }
        }
    }

    // reduce across the 16 tx lanes (each half-warp holds one ty group)
    #pragma unroll
    for (int i = 0; i < 4; i++) {
        float a = aAcc[i], c = cAcc[i];
        #pragma unroll
        for (int off = 8; off > 0; off >>= 1) {
            a += __shfl_xor_sync(0xffffffffu, a, off);
            c += __shfl_xor_sync(0xffffffffu, c, off);
        }
        if (tx == 0) {
            int b = b0 + ty + 8 * i;
            g_A[l * Bn + b] = 0.5f * a;
            g_C[l * Bn + b] = 0.5f * c;
        }
    }
}

// ==================== kernel 3: mask + softmax + blend ====================
// warp per (l, b) row; float4 vectorized over D.
__global__ __launch_bounds__(256) void blend_kernel(const float* __restrict__ S,
                                                    const int* __restrict__ sizes,
                                                    float* __restrict__ out) {
    const int l    = blockIdx.y;
    const int warp = threadIdx.x >> 5;
    const int lane = threadIdx.x & 31;
    const int b    = blockIdx.x * 8 + warp;

    const float inv_d = 1.0f / 300.0f;
    const int sz = sizes[b];

    float l1 = g_A[l * Bn + b] * inv_d;                                     // self: always valid
    float l0 = (l >= 1 && l < sz)      ? g_C[l * Bn + b] * inv_d       : -INFINITY; // prev
    float l2 = (l < Ln - 1 && l < sz - 1) ? g_C[(l + 1) * Bn + b] * inv_d : -INFINITY; // next

    float m  = fmaxf(l1, fmaxf(l0, l2));
    float e0 = expf(l0 - m), e1 = expf(l1 - m), e2 = expf(l2 - m);
    float inv = 1.0f / (e0 + e1 + e2);
    float w0 = e0 * inv, w1 = e1 * inv, w2 = e2 * inv;

    const size_t roff  = ((size_t)l * Bn + b) * Dn;
    const size_t slab  = (size_t)Bn * Dn;
    const float4* cur = (const float4*)(S + roff);
    float4*       o   = (float4*)(out + roff);
    const bool hasP = (l > 0), hasN = (l < Ln - 1);
    const float4* prv = hasP ? (const float4*)(S + roff - slab) : cur;
    const float4* nxt = hasN ? (const float4*)(S + roff + slab) : cur;

    const float4 z = make_float4(0.f, 0.f, 0.f, 0.f);
    for (int c = lane; c < 75; c += 32) {
        float4 x = cur[c];
        float4 p = hasP ? prv[c] : z;
        float4 n = hasN ? nxt[c] : z;
        float4 r;
        r.x = w1 * x.x + w0 * p.x + w2 * n.x;
        r.y = w1 * x.y + w0 * p.y + w2 * n.y;
        r.z = w1 * x.z + w0 * p.z + w2 * n.z;
        r.w = w1 * x.w + w0 * p.w + w2 * n.w;
        o[c] = r;
    }
}

// ==================== launch ====================
extern "C" void kernel_launch(void* const* d_in, const int* in_sizes, int n_in,
                              void* d_out, int out_size) {
    const float* S     = (const float*)d_in[0];  // [L, B, D] fp32
    const int*   sizes = (const int*)d_in[1];    // [B] int32
    const float* W     = (const float*)d_in[2];  // [D, D] fp32
    float*       out   = (float*)d_out;          // [L, B, D] fp32
    (void)in_sizes; (void)n_in; (void)out_size;

    symW_kernel<<<(DP * DP + 255) / 256, 256>>>(W);

    dim3 g2(Bn / BT, Ln);       // (128, 128)
    score_kernel<<<g2, 128>>>(S);

    dim3 g3(Bn / 8, Ln);        // (512, 128)
    blend_kernel<<<g3, 256>>>(S, sizes, out);
}

// round 3
// speedup vs baseline: 5.2509x; 5.2509x over previous
#include <cuda_runtime.h>
#include <cuda_bf16.h>
#include <math.h>
#include <stdint.h>

#define Ln 128
#define Bn 4096
#define Dn 300
#define KP 320
#define NP 320
#define NTILES 4096
#define NCH 160                 // n-cols per chunk (2 chunks)
#define XROW 656                // 320 bf16 = 640B + 16B pad
#define WROW 336                // 160 bf16 = 320B + 16B pad
#define SM_X  0
#define SM_W  83968             // 128*656
#define SM_RA 191488            // 83968 + 320*336
#define SM_RC 192512
#define DYN_SMEM 193536

// ---------------- device scratch ----------------
__device__ __align__(16) __nv_bfloat16 g_Wbf[KP * NP]; // symmetrized, padded, bf16 [k][n]
__device__ float g_A[Ln * Bn];
__device__ float g_C[Ln * Bn];

__device__ __forceinline__ uint32_t smem_to_u32(const void* p) {
    uint32_t a;
    asm("{ .reg .u64 t; cvta.to.shared.u64 t, %1; cvt.u32.u64 %0, t; }" : "=r"(a) : "l"(p));
    return a;
}

#define LDSM_X4(r, addr)                                                        \
    asm volatile("ldmatrix.sync.aligned.m8n8.x4.shared.b16 {%0,%1,%2,%3}, [%4];"\
        : "=r"((r)[0]),"=r"((r)[1]),"=r"((r)[2]),"=r"((r)[3]) : "r"(addr))
#define LDSM_X4T(r, addr)                                                       \
    asm volatile("ldmatrix.sync.aligned.m8n8.x4.trans.shared.b16 {%0,%1,%2,%3}, [%4];"\
        : "=r"((r)[0]),"=r"((r)[1]),"=r"((r)[2]),"=r"((r)[3]) : "r"(addr))
#define MMA16816(d, a, b0, b1)                                                  \
    asm volatile("mma.sync.aligned.m16n8k16.row.col.f32.bf16.bf16.f32 "         \
        "{%0,%1,%2,%3}, {%4,%5,%6,%7}, {%8,%9}, {%0,%1,%2,%3};"                 \
        : "+f"((d)[0]),"+f"((d)[1]),"+f"((d)[2]),"+f"((d)[3])                   \
        : "r"((a)[0]),"r"((a)[1]),"r"((a)[2]),"r"((a)[3]), "r"(b0),"r"(b1))
#define CP_ASYNC16(dst, src)                                                    \
    asm volatile("cp.async.cg.shared.global [%0], [%1], 16;" :: "r"(dst), "l"(src) : "memory")

// ============ kernel 1: bf16 padded symmetric W image ============
__global__ void prepW_kernel(const float* __restrict__ W) {
    int idx = blockIdx.x * 256 + threadIdx.x;
    if (idx >= KP * NP) return;
    int k = idx / NP, n = idx % NP;
    float v = 0.0f;
    if (k < Dn && n < Dn) v = W[k * Dn + n] + W[n * Dn + k];
    g_Wbf[idx] = __float2bfloat16(v);
}

// ============ kernel 2: HMMA GEMM + fused score dots ============
__global__ __launch_bounds__(256, 1) void mma_score_kernel(const float* __restrict__ S) {
    extern __shared__ __align__(16) char smem[];
    const uint32_t sb   = smem_to_u32(smem);
    const int tid  = threadIdx.x;
    const int lane = tid & 31;
    const int wid  = tid >> 5;
    const int wm   = wid & 3;           // 0..3 -> 32-row slice
    const int wn   = wid >> 2;          // 0..1 -> 80-col slice (within chunk)
    const int r0   = 32 * wm;
    const int g    = lane >> 2, q = lane & 3;
    const int   tile = blockIdx.x;
    const size_t m0  = (size_t)tile * 128;
    const bool hasPrev = (tile >= 32);

    // ---- stage X tile (128 x 300 fp32 -> bf16, rows padded to 656B, cols 300..327 zero) ----
    for (int idx = tid; idx < 128 * 75; idx += 256) {
        int r = idx / 75, f = idx % 75;
        float4 v = __ldg((const float4*)(S + (m0 + r) * Dn) + f);
        __nv_bfloat162 p0 = __floats2bfloat162_rn(v.x, v.y);
        __nv_bfloat162 p1 = __floats2bfloat162_rn(v.z, v.w);
        uint2 pk = make_uint2(*(uint32_t*)&p0, *(uint32_t*)&p1);
        *(uint2*)(smem + SM_X + r * XROW + f * 8) = pk;
    }
    for (int idx = tid; idx < 128 * 14; idx += 256) {
        int r = idx / 14, w = idx % 14;
        *(uint32_t*)(smem + SM_X + r * XROW + 600 + w * 4) = 0u;
    }

    // ldmatrix base addresses
    const uint32_t aBase0 = sb + SM_X + (r0 + (lane & 15)) * XROW + (lane >> 4) * 16;
    const uint32_t aBase1 = aBase0 + 16 * XROW;
    const uint32_t bBase  = sb + SM_W + (lane & 15) * WROW + (80 * wn + (lane >> 4) * 8) * 2;

    float aAcc[2][2] = {{0.f,0.f},{0.f,0.f}};
    float cAcc[2][2] = {{0.f,0.f},{0.f,0.f}};

    for (int ch = 0; ch < 2; ch++) {
        const int n0 = ch * NCH;
        __syncthreads();  // X staged / previous chunk's smem reads done
        // ---- stage W chunk [320 k][160 n] via cp.async ----
        for (int idx = tid; idx < 320 * 20; idx += 256) {
            int k = idx / 20, sg = idx % 20;
            uint32_t dst = sb + SM_W + k * WROW + sg * 16;
            const char* src = (const char*)g_Wbf + k * 640 + n0 * 2 + sg * 16;
            CP_ASYNC16(dst, src);
        }
        asm volatile("cp.async.commit_group;" ::: "memory");
        asm volatile("cp.async.wait_group 0;" ::: "memory");
        __syncthreads();

        float acc[2][10][4];
        #pragma unroll
        for (int t = 0; t < 2; t++)
            #pragma unroll
            for (int s = 0; s < 10; s++)
                #pragma unroll
                for (int i = 0; i < 4; i++) acc[t][s][i] = 0.f;

        // ---- K loop: 20 steps of k16 ----
        #pragma unroll 4
        for (int ks = 0; ks < 20; ks++) {
            uint32_t a0[4], a1[4], b[5][4];
            LDSM_X4(a0, aBase0 + ks * 32);
            LDSM_X4(a1, aBase1 + ks * 32);
            const uint32_t bk = bBase + ks * 16 * WROW;
            #pragma unroll
            for (int j = 0; j < 5; j++) LDSM_X4T(b[j], bk + j * 32);
            #pragma unroll
            for (int s = 0; s < 10; s++) {
                const uint32_t b0 = b[s >> 1][(s & 1) * 2];
                const uint32_t b1 = b[s >> 1][(s & 1) * 2 + 1];
                MMA16816(acc[0][s], a0, b0, b1);
                MMA16816(acc[1][s], a1, b0, b1);
            }
        }

        // ---- fused dot epilogue on fragments ----
        #pragma unroll
        for (int t = 0; t < 2; t++) {
            const int rowA = r0 + 16 * t + g;
            const int rowB = rowA + 8;
            const float* pA = S + (m0 + rowA - (size_t)Bn) * Dn;
            const float* pB = S + (m0 + rowB - (size_t)Bn) * Dn;
            #pragma unroll
            for (int s = 0; s < 10; s++) {
                const int cg = n0 + 80 * wn + 8 * s + 2 * q;
                uint32_t svA = *(const uint32_t*)(smem + SM_X + rowA * XROW + cg * 2);
                uint32_t svB = *(const uint32_t*)(smem + SM_X + rowB * XROW + cg * 2);
                __nv_bfloat162 sA2 = *(__nv_bfloat162*)&svA;
                __nv_bfloat162 sB2 = *(__nv_bfloat162*)&svB;
                aAcc[t][0] = fmaf(__bfloat162float(sA2.x), acc[t][s][0],
                             fmaf(__bfloat162float(sA2.y), acc[t][s][1], aAcc[t][0]));
                aAcc[t][1] = fmaf(__bfloat162float(sB2.x), acc[t][s][2],
                             fmaf(__bfloat162float(sB2.y), acc[t][s][3], aAcc[t][1]));
                if (hasPrev) {
                    float2 pvA = __ldg((const float2*)(pA + cg));
                    float2 pvB = __ldg((const float2*)(pB + cg));
                    cAcc[t][0] = fmaf(pvA.x, acc[t][s][0], fmaf(pvA.y, acc[t][s][1], cAcc[t][0]));
                    cAcc[t][1] = fmaf(pvB.x, acc[t][s][2], fmaf(pvB.y, acc[t][s][3], cAcc[t][1]));
                }
            }
        }
    }

    // ---- reduce over q lanes, then over the 2 n-warps via smem ----
    float* sRA = (float*)(smem + SM_RA);   // [2][128]
    float* sRC = (float*)(smem + SM_RC);   // [2][128]
    #pragma unroll
    for (int t = 0; t < 2; t++)
        #pragma unroll
        for (int h = 0; h < 2; h++) {
            float a = aAcc[t][h], c = cAcc[t][h];
            a += __shfl_xor_sync(0xffffffffu, a, 1);
            a += __shfl_xor_sync(0xffffffffu, a, 2);
            c += __shfl_xor_sync(0xffffffffu, c, 1);
            c += __shfl_xor_sync(0xffffffffu, c, 2);
            if (q == 0) {
                int row = r0 + 16 * t + 8 * h + g;
                sRA[wn * 128 + row] = a;
                sRC[wn * 128 + row] = c;
            }
        }
    __syncthreads();
    if (tid < 128) {
        float a = sRA[tid] + sRA[128 + tid];
        g_A[m0 + tid] = 0.5f * a;
        if (hasPrev) {
            float c = sRC[tid] + sRC[128 + tid];
            g_C[m0 + tid] = 0.5f * c;
        }
    }
}

// ============ kernel 3: mask + softmax + blend ============
__global__ __launch_bounds__(256) void blend_kernel(const float* __restrict__ S,
                                                    const int* __restrict__ sizes,
                                                    float* __restrict__ out) {
    const int l    = blockIdx.y;
    const int warp = threadIdx.x >> 5;
    const int lane = threadIdx.x & 31;
    const int b    = blockIdx.x * 8 + warp;

    const float inv_d = 1.0f / 300.0f;
    const int sz = sizes[b];

    float l1 = g_A[l * Bn + b] * inv_d;
    float l0 = (l >= 1 && l < sz)         ? g_C[l * Bn + b] * inv_d       : -INFINITY;
    float l2 = (l < Ln - 1 && l < sz - 1) ? g_C[(l + 1) * Bn + b] * inv_d : -INFINITY;

    float mx = fmaxf(l1, fmaxf(l0, l2));
    float e0 = expf(l0 - mx), e1 = expf(l1 - mx), e2 = expf(l2 - mx);
    float inv = 1.0f / (e0 + e1 + e2);
    float w0 = e0 * inv, w1 = e1 * inv, w2 = e2 * inv;

    const size_t roff = ((size_t)l * Bn + b) * Dn;
    const size_t slab = (size_t)Bn * Dn;
    const float4* cur = (const float4*)(S + roff);
    float4*       o   = (float4*)(out + roff);
    const bool hasP = (l > 0), hasN = (l < Ln - 1);
    const float4* prv = hasP ? (const float4*)(S + roff - slab) : cur;
    const float4* nxt = hasN ? (const float4*)(S + roff + slab) : cur;

    const float4 z = make_float4(0.f, 0.f, 0.f, 0.f);
    for (int c = lane; c < 75; c += 32) {
        float4 x = cur[c];
        float4 p = hasP ? prv[c] : z;
        float4 n = hasN ? nxt[c] : z;
        float4 r;
        r.x = w1 * x.x + w0 * p.x + w2 * n.x;
        r.y = w1 * x.y + w0 * p.y + w2 * n.y;
        r.z = w1 * x.z + w0 * p.z + w2 * n.z;
        r.w = w1 * x.w + w0 * p.w + w2 * n.w;
        o[c] = r;
    }
}

// ==================== launch ====================
extern "C" void kernel_launch(void* const* d_in, const int* in_sizes, int n_in,
                              void* d_out, int out_size) {
    const float* S     = (const float*)d_in[0];
    const int*   sizes = (const int*)d_in[1];
    const float* W     = (const float*)d_in[2];
    float*       out   = (float*)d_out;
    (void)in_sizes; (void)n_in; (void)out_size;

    prepW_kernel<<<(KP * NP + 255) / 256, 256>>>(W);

    cudaFuncSetAttribute(mma_score_kernel, cudaFuncAttributeMaxDynamicSharedMemorySize, DYN_SMEM);
    mma_score_kernel<<<NTILES, 256, DYN_SMEM>>>(S);

    dim3 g3(Bn / 8, Ln);
    blend_kernel<<<g3, 256>>>(S, sizes, out);
}